// round 8
// baseline (speedup 1.0000x reference)
#include <cuda_runtime.h>
#include <cuda_bf16.h>
#include <cstdint>

#define NN 8192
#define DD 512
#define LSCALE 2.659f

// ---------------- device scratch ----------------
__device__ __align__(128) signed char g_A[NN * DD];   // quantized normalized img
__device__ __align__(128) signed char g_B[NN * DD];   // quantized normalized txt
__device__ float g_sA[NN], g_sB[NN];                  // per-row quant scales
__device__ float g_rowE[NN], g_rowW[NN], g_colE[NN], g_colW[NN];
__device__ float g_Sinv[NN];
__device__ int   g_lab[NN];
__device__ int   g_hist[128];

// ---------------- asm helpers ----------------
__device__ __forceinline__ uint32_t smem_u32(const void* p) {
    uint32_t a;
    asm("{ .reg .u64 t; cvta.to.shared.u64 t, %1; cvt.u32.u64 %0, t; }" : "=r"(a) : "l"(p));
    return a;
}
#define CP_ASYNC16(dst, src) \
    asm volatile("cp.async.cg.shared.global [%0], [%1], 16;" :: "r"(dst), "l"(src) : "memory")
#define CP_COMMIT() asm volatile("cp.async.commit_group;" ::: "memory")
#define CP_WAIT1()  asm volatile("cp.async.wait_group 1;" ::: "memory")
#define CP_WAIT0()  asm volatile("cp.async.wait_group 0;" ::: "memory")

#define LDSM4(r0, r1, r2, r3, addr) \
    asm volatile("ldmatrix.sync.aligned.m8n8.x4.shared.b16 {%0,%1,%2,%3}, [%4];" \
                 : "=r"(r0), "=r"(r1), "=r"(r2), "=r"(r3) : "r"(addr))

// int8 MMA: s8 fragments have the same layout as f16 m16n8k16 with b16 -> 2 s8
#define MMA16832(d, a, b0, b1) \
    asm volatile("mma.sync.aligned.m16n8k32.row.col.s32.s8.s8.s32 " \
                 "{%0,%1,%2,%3}, {%4,%5,%6,%7}, {%8,%9}, {%0,%1,%2,%3};" \
                 : "+r"((d)[0]), "+r"((d)[1]), "+r"((d)[2]), "+r"((d)[3]) \
                 : "r"((a)[0]), "r"((a)[1]), "r"((a)[2]), "r"((a)[3]), "r"(b0), "r"(b1))

// smem tile: 128 rows x 64 int8 (BK=64), rows padded 64B -> 80B (ldmatrix conflict-free)
#define PITCH   80
#define TILE_B  (128 * PITCH)       // 10240
#define STAGE_B (2 * TILE_B)        // A + B
#define NSTAGE  3
#define SMEM_RED (NSTAGE * STAGE_B)
#define SMEM_TOT (SMEM_RED + 128 * 4 * 8)   // + sLR,sLC,sSA,sSB,sRE,sRW,sCE,sCW

// ---------------------------------------------------------------------------
__global__ void k_init() {            // hist only (1 block)
    if (threadIdx.x < 128) g_hist[threadIdx.x] = 0;
}

// normalize -> int8 quantize with per-row scale
__global__ void k_norm(const float* __restrict__ txt, const float* __restrict__ img) {
    int b = blockIdx.x;
    const float* src;
    signed char* dst;
    float* sc;
    if (b < NN) { src = img + (size_t)b * DD; dst = g_A + (size_t)b * DD; sc = g_sA + b; }
    else { b -= NN; src = txt + (size_t)b * DD; dst = g_B + (size_t)b * DD; sc = g_sB + b; }
    int t = threadIdx.x;
    float4 v = ((const float4*)src)[t];
    float ss = v.x * v.x + v.y * v.y + v.z * v.z + v.w * v.w;
    float mm = fmaxf(fmaxf(fabsf(v.x), fabsf(v.y)), fmaxf(fabsf(v.z), fabsf(v.w)));
    #pragma unroll
    for (int m = 16; m; m >>= 1) {
        ss += __shfl_xor_sync(0xffffffffu, ss, m);
        mm = fmaxf(mm, __shfl_xor_sync(0xffffffffu, mm, m));
    }
    __shared__ float sp[4], sq[4];
    if ((t & 31) == 0) { sp[t >> 5] = ss; sq[t >> 5] = mm; }
    __syncthreads();
    float tot = sp[0] + sp[1] + sp[2] + sp[3];
    float mx = fmaxf(fmaxf(sq[0], sq[1]), fmaxf(sq[2], sq[3]));
    mx = fmaxf(mx, 1e-30f);
    float inv = 1.0f / fmaxf(sqrtf(tot), 1e-12f);
    float qs = 127.0f / mx;                  // quant: q = round(v * 127 / max|v|)
    if (t == 0) *sc = mx * inv * (1.0f / 127.0f);   // scale of normalized vector
    char4 q;
    q.x = (signed char)__float2int_rn(v.x * qs);
    q.y = (signed char)__float2int_rn(v.y * qs);
    q.z = (signed char)__float2int_rn(v.z * qs);
    q.w = (signed char)__float2int_rn(v.w * qs);
    ((char4*)dst)[t] = q;
}

// zero accumulators + label histogram
__global__ void k_lab(const int* __restrict__ labels) {
    int i = blockIdx.x * blockDim.x + threadIdx.x;
    if (i < NN) {
        g_rowE[i] = 0.f; g_rowW[i] = 0.f; g_colE[i] = 0.f; g_colW[i] = 0.f;
        int l = labels[i];
        if (l < -1 || l >= 128) l = -1;
        g_lab[i] = l;
        if (l >= 0) atomicAdd(&g_hist[l], 1);
    }
}

__global__ void k_S() {
    int i = blockIdx.x * blockDim.x + threadIdx.x;
    if (i < NN) {
        int l = g_lab[i];
        g_Sinv[i] = (l < 0) ? 1.0f : 1.0f / (float)g_hist[l];
    }
}

// ---------------------------------------------------------------------------
// int8 IMMA GEMM + fused soft-CE epilogue.
// 128x128 tile, 8 warps (2x4), warp tile 64x32, BK=64, 3-stage cp.async pipeline.
__global__ __launch_bounds__(256, 2) void k_gemm_mma() {
    extern __shared__ __align__(16) char smem[];
    uint32_t sb = smem_u32(smem);
    int* sLR = (int*)(smem + SMEM_RED);
    int* sLC = sLR + 128;
    float* sSA = (float*)(sLC + 128);
    float* sSB = sSA + 128;
    float* sRE = sSB + 128;
    float* sRW = sRE + 128;
    float* sCE = sRW + 128;
    float* sCW = sCE + 128;

    int tid = threadIdx.x, lane = tid & 31, wid = tid >> 5;
    int wy = wid >> 2, wx = wid & 3;          // warp grid 2 (m) x 4 (n)
    int gid = lane >> 2, tig = lane & 3;
    int bm = blockIdx.y * 128, bn = blockIdx.x * 128;

    if (tid < 128) {
        sLR[tid] = g_lab[bm + tid]; sLC[tid] = g_lab[bn + tid];
        sSA[tid] = g_sA[bm + tid] * LSCALE;   // fold logit scale into row scale
        sSB[tid] = g_sB[bn + tid];
        sRE[tid] = 0.f; sRW[tid] = 0.f; sCE[tid] = 0.f; sCW[tid] = 0.f;
    }

    const signed char* Asrc = g_A + (size_t)bm * DD;
    const signed char* Bsrc = g_B + (size_t)bn * DD;

    auto copy_stage = [&](int it) {
        uint32_t dstb = sb + (uint32_t)(it % NSTAGE) * STAGE_B;
        int k0 = it * 64;
        #pragma unroll
        for (int i = 0; i < 2; i++) {
            int idx = tid + 256 * i;              // 0..511
            int row = idx >> 2, c = idx & 3;      // 4 x 16B per 64B row
            CP_ASYNC16(dstb + row * PITCH + c * 16,
                       Asrc + (size_t)row * DD + k0 + c * 16);
            CP_ASYNC16(dstb + TILE_B + row * PITCH + c * 16,
                       Bsrc + (size_t)row * DD + k0 + c * 16);
        }
        CP_COMMIT();
    };

    int acc[4][4][4];
    #pragma unroll
    for (int mf = 0; mf < 4; mf++)
        #pragma unroll
        for (int nf = 0; nf < 4; nf++)
            #pragma unroll
            for (int e = 0; e < 4; e++) acc[mf][nf][e] = 0;

    copy_stage(0);
    copy_stage(1);

    int a_row = (lane & 15);
    uint32_t a_koff = (uint32_t)((lane >> 4) << 4);
    int b_nrow = (lane & 7) + ((lane >> 4) << 3);
    uint32_t b_koff = (uint32_t)(((lane >> 3) & 1) << 4);

    for (int it = 0; it < 8; it++) {
        if (it == 7) CP_WAIT0(); else CP_WAIT1();
        __syncthreads();
        if (it < 6) copy_stage(it + 2);
        uint32_t buf = sb + (uint32_t)(it % NSTAGE) * STAGE_B;

        #pragma unroll
        for (int kk = 0; kk < 2; kk++) {
            uint32_t kb = kk * 32;  // 32 int8 per k-step
            uint32_t bh[8];
            #pragma unroll
            for (int p = 0; p < 2; p++) {
                int n = wx * 32 + p * 16 + b_nrow;
                LDSM4(bh[p * 4 + 0], bh[p * 4 + 1], bh[p * 4 + 2], bh[p * 4 + 3],
                      buf + TILE_B + n * PITCH + kb + b_koff);
            }
            #pragma unroll
            for (int mf = 0; mf < 4; mf++) {
                int r = wy * 64 + mf * 16 + a_row;
                uint32_t ah[4];
                LDSM4(ah[0], ah[1], ah[2], ah[3], buf + r * PITCH + kb + a_koff);
                #pragma unroll
                for (int nf = 0; nf < 4; nf++) {
                    int base = (nf >> 1) * 4 + (nf & 1) * 2;
                    MMA16832(acc[mf][nf], ah, bh[base], bh[base + 1]);
                }
            }
        }
    }
    __syncthreads();

    // ---- fused epilogue ----
    int liA[8], ljA[8];
    float rsA[8], csB[8];
    #pragma unroll
    for (int b = 0; b < 8; b++) {
        int rl = wy * 64 + (b >> 1) * 16 + gid + (b & 1) * 8;
        int cl = wx * 32 + (b >> 1) * 8 + 2 * tig + (b & 1);
        liA[b] = sLR[rl]; ljA[b] = sLC[cl];
        rsA[b] = sSA[rl]; csB[b] = sSB[cl];
    }
    float rE[8], rW[8], cE[8], cW[8];
    #pragma unroll
    for (int b = 0; b < 8; b++) { rE[b] = 0.f; rW[b] = 0.f; cE[b] = 0.f; cW[b] = 0.f; }

    #pragma unroll
    for (int mf = 0; mf < 4; mf++)
        #pragma unroll
        for (int nf = 0; nf < 4; nf++)
            #pragma unroll
            for (int e = 0; e < 4; e++) {
                int h = e >> 1, q = e & 1;
                int rowloc = wy * 64 + mf * 16 + gid + h * 8;
                int colloc = wx * 32 + nf * 8 + 2 * tig + q;
                float l = __int2float_rn(acc[mf][nf][e]) * rsA[mf * 2 + h] * csB[nf * 2 + q];
                float ex = __expf(l - LSCALE);
                int li = liA[mf * 2 + h], lj = ljA[nf * 2 + q];
                bool tm = (bm + rowloc == bn + colloc) || (li >= 0 && li == lj);
                float w = tm ? l : 0.f;
                rE[mf * 2 + h] += ex; rW[mf * 2 + h] += w;
                cE[nf * 2 + q] += ex; cW[nf * 2 + q] += w;
            }

    #pragma unroll
    for (int m = 1; m < 4; m <<= 1)
        #pragma unroll
        for (int b = 0; b < 8; b++) {
            rE[b] += __shfl_xor_sync(0xffffffffu, rE[b], m);
            rW[b] += __shfl_xor_sync(0xffffffffu, rW[b], m);
        }
    if (tig == 0) {
        #pragma unroll
        for (int b = 0; b < 8; b++)
            atomicAdd(&sRE[wy * 64 + (b >> 1) * 16 + gid + (b & 1) * 8], rE[b]);
    } else if (tig == 1) {
        #pragma unroll
        for (int b = 0; b < 8; b++)
            atomicAdd(&sRW[wy * 64 + (b >> 1) * 16 + gid + (b & 1) * 8], rW[b]);
    }

    #pragma unroll
    for (int m = 4; m < 32; m <<= 1)
        #pragma unroll
        for (int b = 0; b < 8; b++) {
            cE[b] += __shfl_xor_sync(0xffffffffu, cE[b], m);
            cW[b] += __shfl_xor_sync(0xffffffffu, cW[b], m);
        }
    if (gid == 0) {
        #pragma unroll
        for (int b = 0; b < 8; b++)
            atomicAdd(&sCE[wx * 32 + (b >> 1) * 8 + 2 * tig + (b & 1)], cE[b]);
    } else if (gid == 1) {
        #pragma unroll
        for (int b = 0; b < 8; b++)
            atomicAdd(&sCW[wx * 32 + (b >> 1) * 8 + 2 * tig + (b & 1)], cW[b]);
    }
    __syncthreads();

    if (tid < 128) {
        atomicAdd(&g_rowE[bm + tid], sRE[tid]);
        atomicAdd(&g_rowW[bm + tid], sRW[tid]);
    } else {
        int c = tid - 128;
        atomicAdd(&g_colE[bn + c], sCE[c]);
        atomicAdd(&g_colW[bn + c], sCW[c]);
    }
}

// ---------------------------------------------------------------------------
__global__ void k_final(float* __restrict__ out) {
    int t = threadIdx.x;
    float s = 0.f;
    for (int i = t; i < NN; i += 256) {
        float si = g_Sinv[i];
        float li = logf(g_rowE[i]) + LSCALE - g_rowW[i] * si;
        float lt = logf(g_colE[i]) + LSCALE - g_colW[i] * si;
        s += 0.5f * (li + lt);
    }
    __shared__ float red[256];
    red[t] = s;
    __syncthreads();
    for (int m = 128; m; m >>= 1) {
        if (t < m) red[t] += red[t + m];
        __syncthreads();
    }
    if (t == 0) out[0] = red[0] / (float)NN;
}

// ---------------------------------------------------------------------------
extern "C" void kernel_launch(void* const* d_in, const int* in_sizes, int n_in,
                              void* d_out, int out_size) {
    const float* txt = (const float*)d_in[0];
    const float* img = (const float*)d_in[1];
    const int* labels = (const int*)d_in[2];
    float* out = (float*)d_out;

    static int smem_set = 0;
    if (!smem_set) {
        cudaFuncSetAttribute(k_gemm_mma, cudaFuncAttributeMaxDynamicSharedMemorySize, SMEM_TOT);
        smem_set = 1;
    }

    k_init<<<1, 128>>>();
    k_norm<<<2 * NN, 128>>>(txt, img);
    k_lab<<<(NN + 255) / 256, 256>>>(labels);
    k_S<<<(NN + 255) / 256, 256>>>();
    dim3 g(NN / 128, NN / 128);
    k_gemm_mma<<<g, 256, SMEM_TOT>>>();
    k_final<<<1, 256>>>(out);
}

// round 9
// speedup vs baseline: 2.0206x; 2.0206x over previous
#include <cuda_runtime.h>
#include <cuda_bf16.h>
#include <cstdint>

#define NN 8192
#define DD 512
#define LSCALE 2.659f

// ---------------- device scratch ----------------
__device__ __align__(128) __nv_bfloat16 g_A[NN * DD];   // normalized img, bf16
__device__ __align__(128) __nv_bfloat16 g_B[NN * DD];   // normalized txt, bf16
__device__ float g_rowE[NN], g_rowW[NN], g_colE[NN], g_colW[NN];
__device__ int   g_lab[NN];
__device__ int   g_hist[128];

// ---------------- asm helpers ----------------
__device__ __forceinline__ uint32_t smem_u32(const void* p) {
    uint32_t a;
    asm("{ .reg .u64 t; cvta.to.shared.u64 t, %1; cvt.u32.u64 %0, t; }" : "=r"(a) : "l"(p));
    return a;
}
#define CP_ASYNC16(dst, src) \
    asm volatile("cp.async.cg.shared.global [%0], [%1], 16;" :: "r"(dst), "l"(src) : "memory")
#define CP_COMMIT() asm volatile("cp.async.commit_group;" ::: "memory")
#define CP_WAIT1()  asm volatile("cp.async.wait_group 1;" ::: "memory")
#define CP_WAIT0()  asm volatile("cp.async.wait_group 0;" ::: "memory")

#define LDSM4(r0, r1, r2, r3, addr) \
    asm volatile("ldmatrix.sync.aligned.m8n8.x4.shared.b16 {%0,%1,%2,%3}, [%4];" \
                 : "=r"(r0), "=r"(r1), "=r"(r2), "=r"(r3) : "r"(addr))

#define MMA16816(d, a, b0, b1) \
    asm volatile("mma.sync.aligned.m16n8k16.row.col.f32.bf16.bf16.f32 " \
                 "{%0,%1,%2,%3}, {%4,%5,%6,%7}, {%8,%9}, {%0,%1,%2,%3};" \
                 : "+f"((d)[0]), "+f"((d)[1]), "+f"((d)[2]), "+f"((d)[3]) \
                 : "r"((a)[0]), "r"((a)[1]), "r"((a)[2]), "r"((a)[3]), "r"(b0), "r"(b1))

// smem tile geometry: rows padded 64B -> 80B (bank-conflict-free ldmatrix)
#define PITCH   80
#define TILE_B  (128 * PITCH)       // 10240 bytes (128 rows x 32 bf16)
#define STAGE_B (2 * TILE_B)        // A + B
#define NSTAGE  3
#define SMEM_RED (NSTAGE * STAGE_B)
#define SMEM_TOT (SMEM_RED + 128 * 4 * 6)

// ---------------------------------------------------------------------------
__global__ void k_init() {            // hist zero only
    if (threadIdx.x < 128) g_hist[threadIdx.x] = 0;
}

// normalize -> bf16
__global__ void k_norm(const float* __restrict__ txt, const float* __restrict__ img) {
    int b = blockIdx.x;
    const float* src;
    __nv_bfloat16* dst;
    if (b < NN) { src = img + (size_t)b * DD; dst = g_A + (size_t)b * DD; }
    else { b -= NN; src = txt + (size_t)b * DD; dst = g_B + (size_t)b * DD; }
    int t = threadIdx.x;
    float4 v = ((const float4*)src)[t];
    float ss = v.x * v.x + v.y * v.y + v.z * v.z + v.w * v.w;
    #pragma unroll
    for (int m = 16; m; m >>= 1) ss += __shfl_xor_sync(0xffffffffu, ss, m);
    __shared__ float sp[4];
    if ((t & 31) == 0) sp[t >> 5] = ss;
    __syncthreads();
    float inv = 1.0f / fmaxf(sqrtf(sp[0] + sp[1] + sp[2] + sp[3]), 1e-12f);
    __nv_bfloat162* dp = (__nv_bfloat162*)dst;
    dp[t * 2 + 0] = __nv_bfloat162(__float2bfloat16(v.x * inv), __float2bfloat16(v.y * inv));
    dp[t * 2 + 1] = __nv_bfloat162(__float2bfloat16(v.z * inv), __float2bfloat16(v.w * inv));
}

// zero accumulators + labels + histogram
__global__ void k_lab(const int* __restrict__ labels) {
    int i = blockIdx.x * blockDim.x + threadIdx.x;
    if (i < NN) {
        g_rowE[i] = 0.f; g_rowW[i] = 0.f; g_colE[i] = 0.f; g_colW[i] = 0.f;
        int l = labels[i];
        if (l < -1 || l >= 128) l = -1;
        g_lab[i] = l;
        if (l >= 0) atomicAdd(&g_hist[l], 1);
    }
}

// ---------------------------------------------------------------------------
// bf16 HMMA GEMM + fused soft-CE epilogue.
// 128x128 tile, 8 warps (2x4), warp tile 64x32, BK=32, 3-stage cp.async pipeline.
__global__ __launch_bounds__(256, 2) void k_gemm_mma() {
    extern __shared__ __align__(16) char smem[];
    uint32_t sb = smem_u32(smem);
    int* sLR = (int*)(smem + SMEM_RED);
    int* sLC = sLR + 128;
    float* sRE = (float*)(sLC + 128);
    float* sRW = sRE + 128;
    float* sCE = sRW + 128;
    float* sCW = sCE + 128;

    int tid = threadIdx.x, lane = tid & 31, wid = tid >> 5;
    int wy = wid >> 2, wx = wid & 3;          // warp grid 2 (m) x 4 (n)
    int gid = lane >> 2, tig = lane & 3;
    int bm = blockIdx.y * 128, bn = blockIdx.x * 128;

    if (tid < 128) {
        sLR[tid] = g_lab[bm + tid]; sLC[tid] = g_lab[bn + tid];
        sRE[tid] = 0.f; sRW[tid] = 0.f; sCE[tid] = 0.f; sCW[tid] = 0.f;
    }

    const __nv_bfloat16* Asrc = g_A + (size_t)bm * DD;
    const __nv_bfloat16* Bsrc = g_B + (size_t)bn * DD;

    auto copy_stage = [&](int it) {
        uint32_t dstb = sb + (uint32_t)(it % NSTAGE) * STAGE_B;
        int k0 = it * 32;
        #pragma unroll
        for (int i = 0; i < 2; i++) {
            int idx = tid + 256 * i;              // 0..511
            int row = idx >> 2, c = idx & 3;      // 4 x 16B per 64B row
            CP_ASYNC16(dstb + row * PITCH + c * 16,
                       Asrc + (size_t)row * DD + k0 + c * 8);
            CP_ASYNC16(dstb + TILE_B + row * PITCH + c * 16,
                       Bsrc + (size_t)row * DD + k0 + c * 8);
        }
        CP_COMMIT();
    };

    float acc[4][4][4];
    #pragma unroll
    for (int mf = 0; mf < 4; mf++)
        #pragma unroll
        for (int nf = 0; nf < 4; nf++)
            #pragma unroll
            for (int e = 0; e < 4; e++) acc[mf][nf][e] = 0.f;

    copy_stage(0);
    copy_stage(1);

    int a_row = (lane & 15);
    uint32_t a_koff = (uint32_t)((lane >> 4) << 4);
    int b_nrow = (lane & 7) + ((lane >> 4) << 3);
    uint32_t b_koff = (uint32_t)(((lane >> 3) & 1) << 4);

    for (int it = 0; it < 16; it++) {
        if (it == 15) CP_WAIT0(); else CP_WAIT1();
        __syncthreads();
        if (it < 14) copy_stage(it + 2);
        uint32_t buf = sb + (uint32_t)(it % NSTAGE) * STAGE_B;

        #pragma unroll
        for (int kk = 0; kk < 2; kk++) {
            uint32_t kb = kk * 32;  // 16 bf16 in bytes
            uint32_t bh[8];
            #pragma unroll
            for (int p = 0; p < 2; p++) {
                int n = wx * 32 + p * 16 + b_nrow;
                LDSM4(bh[p * 4 + 0], bh[p * 4 + 1], bh[p * 4 + 2], bh[p * 4 + 3],
                      buf + TILE_B + n * PITCH + kb + b_koff);
            }
            #pragma unroll
            for (int mf = 0; mf < 4; mf++) {
                int r = wy * 64 + mf * 16 + a_row;
                uint32_t ah[4];
                LDSM4(ah[0], ah[1], ah[2], ah[3], buf + r * PITCH + kb + a_koff);
                #pragma unroll
                for (int nf = 0; nf < 4; nf++) {
                    int base = (nf >> 1) * 4 + (nf & 1) * 2;
                    MMA16816(acc[mf][nf], ah, bh[base], bh[base + 1]);
                }
            }
        }
    }
    __syncthreads();

    // ---- fused epilogue ----
    int liA[8], ljA[8];
    #pragma unroll
    for (int b = 0; b < 8; b++) {
        liA[b] = sLR[wy * 64 + (b >> 1) * 16 + gid + (b & 1) * 8];
        ljA[b] = sLC[wx * 32 + (b >> 1) * 8 + 2 * tig + (b & 1)];
    }
    float rE[8], rW[8], cE[8], cW[8];
    #pragma unroll
    for (int b = 0; b < 8; b++) { rE[b] = 0.f; rW[b] = 0.f; cE[b] = 0.f; cW[b] = 0.f; }

    #pragma unroll
    for (int mf = 0; mf < 4; mf++)
        #pragma unroll
        for (int nf = 0; nf < 4; nf++)
            #pragma unroll
            for (int e = 0; e < 4; e++) {
                int h = e >> 1, q = e & 1;
                int rowloc = wy * 64 + mf * 16 + gid + h * 8;
                int colloc = wx * 32 + nf * 8 + 2 * tig + q;
                float l = acc[mf][nf][e] * LSCALE;
                float ex = __expf(l - LSCALE);
                int li = liA[mf * 2 + h], lj = ljA[nf * 2 + q];
                bool tm = (bm + rowloc == bn + colloc) || (li >= 0 && li == lj);
                float w = tm ? l : 0.f;
                rE[mf * 2 + h] += ex; rW[mf * 2 + h] += w;
                cE[nf * 2 + q] += ex; cW[nf * 2 + q] += w;
            }

    #pragma unroll
    for (int m = 1; m < 4; m <<= 1)
        #pragma unroll
        for (int b = 0; b < 8; b++) {
            rE[b] += __shfl_xor_sync(0xffffffffu, rE[b], m);
            rW[b] += __shfl_xor_sync(0xffffffffu, rW[b], m);
        }
    if (tig == 0) {
        #pragma unroll
        for (int b = 0; b < 8; b++)
            atomicAdd(&sRE[wy * 64 + (b >> 1) * 16 + gid + (b & 1) * 8], rE[b]);
    } else if (tig == 1) {
        #pragma unroll
        for (int b = 0; b < 8; b++)
            atomicAdd(&sRW[wy * 64 + (b >> 1) * 16 + gid + (b & 1) * 8], rW[b]);
    }

    #pragma unroll
    for (int m = 4; m < 32; m <<= 1)
        #pragma unroll
        for (int b = 0; b < 8; b++) {
            cE[b] += __shfl_xor_sync(0xffffffffu, cE[b], m);
            cW[b] += __shfl_xor_sync(0xffffffffu, cW[b], m);
        }
    if (gid == 0) {
        #pragma unroll
        for (int b = 0; b < 8; b++)
            atomicAdd(&sCE[wx * 32 + (b >> 1) * 8 + 2 * tig + (b & 1)], cE[b]);
    } else if (gid == 1) {
        #pragma unroll
        for (int b = 0; b < 8; b++)
            atomicAdd(&sCW[wx * 32 + (b >> 1) * 8 + 2 * tig + (b & 1)], cW[b]);
    }
    __syncthreads();

    if (tid < 128) {
        atomicAdd(&g_rowE[bm + tid], sRE[tid]);
        atomicAdd(&g_rowW[bm + tid], sRW[tid]);
    } else {
        int c = tid - 128;
        atomicAdd(&g_colE[bn + c], sCE[c]);
        atomicAdd(&g_colW[bn + c], sCW[c]);
    }
}

// ---------------------------------------------------------------------------
// final reduction; computes Sinv inline from histogram (k_S folded in)
__global__ void k_final(float* __restrict__ out) {
    int t = threadIdx.x;
    float s = 0.f;
    for (int i = t; i < NN; i += 256) {
        int l = g_lab[i];
        float si = (l < 0) ? 1.0f : 1.0f / (float)g_hist[l];
        float li = logf(g_rowE[i]) + LSCALE - g_rowW[i] * si;
        float lt = logf(g_colE[i]) + LSCALE - g_colW[i] * si;
        s += 0.5f * (li + lt);
    }
    __shared__ float red[256];
    red[t] = s;
    __syncthreads();
    for (int m = 128; m; m >>= 1) {
        if (t < m) red[t] += red[t + m];
        __syncthreads();
    }
    if (t == 0) out[0] = red[0] / (float)NN;
}

// ---------------------------------------------------------------------------
extern "C" void kernel_launch(void* const* d_in, const int* in_sizes, int n_in,
                              void* d_out, int out_size) {
    const float* txt = (const float*)d_in[0];
    const float* img = (const float*)d_in[1];
    const int* labels = (const int*)d_in[2];
    float* out = (float*)d_out;

    static int smem_set = 0;
    if (!smem_set) {
        cudaFuncSetAttribute(k_gemm_mma, cudaFuncAttributeMaxDynamicSharedMemorySize, SMEM_TOT);
        smem_set = 1;
    }

    k_init<<<1, 128>>>();
    k_norm<<<2 * NN, 128>>>(txt, img);
    k_lab<<<(NN + 255) / 256, 256>>>(labels);
    dim3 g(NN / 128, NN / 128);
    k_gemm_mma<<<g, 256, SMEM_TOT>>>();
    k_final<<<1, 256>>>(out);
}